// round 14
// baseline (speedup 1.0000x reference)
#include <cuda_runtime.h>
#include <cuda.h>
#include <cstdint>

#define D    100
#define Kn   32
#define NBA  2            // attn nodes per block -> M = 64
#define M    64
#define AW   128          // A row stride (512 B -> TMA 128B-aligned rows)
#define TA   128
#define NMAX 50000
#define NT   13
#define KTB  7            // attn k tiles of 16 (112, zero-padded from 101)
#define SSW  112
// mlp
#define MN   64
#define SA2  212
#define KT2  25

__device__ float g_msg[NMAX * D];
__device__ uint2  g_W1f[NT * KTB * 32];
__device__ float2 g_W2f[NT * KT2 * 32];

__device__ __forceinline__ float tanh_fast(float x) {
    float r; asm("tanh.approx.f32 %0, %1;" : "=f"(r) : "f"(x)); return r;
}
__device__ __forceinline__ uint32_t f2tf32(float x) {
    uint32_t r; asm("cvt.rna.tf32.f32 %0, %1;" : "=r"(r) : "f"(x)); return r;
}
__device__ __forceinline__ uint32_t pack_bf16(float lo, float hi) {
    uint32_t r; asm("cvt.rn.bf16x2.f32 %0, %1, %2;" : "=r"(r) : "f"(hi), "f"(lo)); return r;
}
__device__ __forceinline__ uint32_t smem_u32(const void* p) {
    uint32_t a;
    asm("{ .reg .u64 t; cvta.to.shared.u64 t, %1; cvt.u32.u64 %0, t; }" : "=r"(a) : "l"(p));
    return a;
}
__device__ __forceinline__ void mma_bf16(float& c0, float& c1, float& c2, float& c3,
                                         uint32_t a0, uint32_t a1, uint32_t a2, uint32_t a3,
                                         uint32_t b0, uint32_t b1) {
    asm volatile(
        "mma.sync.aligned.m16n8k16.row.col.f32.bf16.bf16.f32 "
        "{%0,%1,%2,%3}, {%4,%5,%6,%7}, {%8,%9}, {%0,%1,%2,%3};"
        : "+f"(c0), "+f"(c1), "+f"(c2), "+f"(c3)
        : "r"(a0), "r"(a1), "r"(a2), "r"(a3), "r"(b0), "r"(b1));
}
__device__ __forceinline__ void mma_tf32(float& c0, float& c1, float& c2, float& c3,
                                         uint32_t a0, uint32_t a1, uint32_t a2, uint32_t a3,
                                         uint32_t b0, uint32_t b1) {
    asm volatile(
        "mma.sync.aligned.m16n8k8.row.col.f32.tf32.tf32.f32 "
        "{%0,%1,%2,%3}, {%4,%5,%6,%7}, {%8,%9}, {%0,%1,%2,%3};"
        : "+f"(c0), "+f"(c1), "+f"(c2), "+f"(c3)
        : "r"(a0), "r"(a1), "r"(a2), "r"(a3), "r"(b0), "r"(b1));
}
#define MBAR_INIT(a, c) asm volatile("mbarrier.init.shared.b64 [%0], %1;" :: "r"(a), "r"(c) : "memory")
#define MBAR_EXPECT_TX(a, b) asm volatile("mbarrier.arrive.expect_tx.shared.b64 _, [%0], %1;" :: "r"(a), "r"(b) : "memory")
#define MBAR_INVAL(a) asm volatile("mbarrier.inval.shared.b64 [%0];" :: "r"(a) : "memory")
#define MBAR_WAIT(a, ph) do {                                                              \
    asm volatile("{\n\t.reg .pred P1;\n\tWL_%=:\n\t"                                       \
        "mbarrier.try_wait.parity.shared.b64 P1, [%0], %1, 0x989680;\n\t"                  \
        "@P1 bra.uni WD_%=;\n\tbra.uni WL_%=;\n\tWD_%=:\n\t}"                              \
        :: "r"(a), "r"(ph) : "memory"); } while (0)
#define TMA_ROW(dst, map, row, mbar)                                                       \
    asm volatile("cp.async.bulk.tensor.2d.shared::cta.global.tile.mbarrier::complete_tx::bytes " \
        "[%0], [%1, {%2, %3}], [%4];"                                                      \
        :: "r"(dst), "l"(map), "r"(0), "r"(row), "r"(mbar) : "memory")

// ---------------------------------------------------------------------------
__global__ void prep_kernel(const float* __restrict__ W1w, const float* __restrict__ W2w)
{
    int idx = blockIdx.x * blockDim.x + threadIdx.x;
    if (idx < NT * KTB * 32) {
        int lane = idx & 31, kk = (idx >> 5) % KTB, n = idx / (32 * KTB);
        int g = lane >> 2, t = lane & 3;
        int j = n * 8 + g;
        auto w1 = [&](int k) -> float {
            return (j < D && k < D + 1) ? W1w[k * D + j] : 0.f;
        };
        int k0 = kk * 16 + 2 * t;
        uint2 o;
        o.x = pack_bf16(w1(k0),     w1(k0 + 1));
        o.y = pack_bf16(w1(k0 + 8), w1(k0 + 9));
        g_W1f[idx] = o;
    } else if (idx < NT * KTB * 32 + NT * KT2 * 32) {
        int i2 = idx - NT * KTB * 32;
        int lane = i2 & 31, kk = (i2 >> 5) % KT2, n = i2 / (32 * KT2);
        int g = lane >> 2, t = lane & 3;
        int j = n * 8 + g;
        int k0 = kk * 8 + t, k1 = k0 + 4;
        float v0 = (j < D) ? W2w[k0 * D + j] : 0.f;
        float v1 = (j < D) ? W2w[k1 * D + j] : 0.f;
        float2 o;
        o.x = __uint_as_float(f2tf32(v0));
        o.y = __uint_as_float(f2tf32(v1));
        g_W2f[i2] = o;
    }
}

__global__ void dummy_kernel() {}

template<int N0, int NB>
__device__ __forceinline__ void gemm_group(const uint32_t af[KTB][4],
                                           const float* bsh, const float* q1s,
                                           int lane, int ja, int jb,
                                           float& p0, float& p1)
{
    float acc[NB][4];
    #pragma unroll
    for (int n = 0; n < NB; ++n) {
        float ba = bsh[(N0 + n) * 8 + ja], bb = bsh[(N0 + n) * 8 + jb];
        acc[n][0] = ba; acc[n][1] = bb; acc[n][2] = ba; acc[n][3] = bb;
    }
    #pragma unroll
    for (int kk = 0; kk < KTB; ++kk) {
        #pragma unroll
        for (int n = 0; n < NB; ++n) {
            uint2 b = __ldg(&g_W1f[((N0 + n) * KTB + kk) * 32 + lane]);
            mma_bf16(acc[n][0], acc[n][1], acc[n][2], acc[n][3],
                     af[kk][0], af[kk][1], af[kk][2], af[kk][3], b.x, b.y);
        }
    }
    #pragma unroll
    for (int n = 0; n < NB; ++n) {
        float qa = q1s[(N0 + n) * 8 + ja], qb = q1s[(N0 + n) * 8 + jb];
        p0 += qa * tanh_fast(acc[n][0]) + qb * tanh_fast(acc[n][1]);
        p1 += qa * tanh_fast(acc[n][2]) + qb * tanh_fast(acc[n][3]);
    }
}

// ---------------------------------------------------------------------------
// Kernel A: 2 nodes/block (M=64), 128 threads; gather via TMA row loads.
// Rows 512B-aligned for TMA; cols 101..111 zero-filled (pack reads to 111).
// ---------------------------------------------------------------------------
__global__ void __launch_bounds__(TA, 6)
attn_kernel(const __grid_constant__ CUtensorMap emb_map,
            const int* __restrict__ nei, const float* __restrict__ wei,
            const float* __restrict__ s_vec,
            const float* __restrict__ W1b, const float* __restrict__ q1w, int Ntot)
{
    extern __shared__ __align__(128) float sm[];
    float* A    = sm;                    // [M][AW]  (TMA fills cols 0..99)
    float* q1s  = A + M * AW;            // [104]
    float* bsh  = q1s + 104;             // [104]
    float* ssx  = bsh + 104;             // [NBA][SSW]
    float* score= ssx + NBA * SSW;       // [M]
    int*   nbid = (int*)(score + M);     // [M]
    unsigned long long* mbar = (unsigned long long*)(nbid + M);

    const int tid  = threadIdx.x;
    const int wid  = tid >> 5;
    const int lane = tid & 31;
    const int g    = lane >> 2;
    const int t    = lane & 3;
    const int node0 = blockIdx.x * NBA;
    if (node0 >= Ntot) return;

    const uint32_t mbar_a = smem_u32(mbar);

    if (tid == 0) MBAR_INIT(mbar_a, 1);
    if (tid < M) {
        int r = tid, node = r >> 5, k = r & 31;
        int nn = node0 + node; if (nn >= Ntot) nn = Ntot - 1;
        nbid[r] = nei[nn * Kn + k];
        float* ar = &A[r * AW];
        ar[100] = wei[nn * Kn + k];
        #pragma unroll
        for (int z = 101; z < 112; ++z) ar[z] = 0.f;   // pack reads cols <=111
    }
    if (tid < 104) {
        q1s[tid] = (tid < D) ? q1w[tid] : 0.f;
        bsh[tid] = (tid < D) ? W1b[tid] : 0.f;
    }
    for (int i = tid; i < NBA * SSW; i += TA) {
        int node = i / SSW, d = i - node * SSW;
        int nn = node0 + node; if (nn >= Ntot) nn = Ntot - 1;
        ssx[i] = (d < D) ? s_vec[nn * D + d] : (d == D ? 1.f : 0.f);
    }
    __syncthreads();

    // ---- TMA gather: 64 row loads (400B each), single issuing thread ----
    if (tid == 0) {
        MBAR_EXPECT_TX(mbar_a, M * D * 4);
        const uint32_t abase = smem_u32(A);
        #pragma unroll 4
        for (int r = 0; r < M; ++r)
            TMA_ROW(abase + (uint32_t)r * (AW * 4u), &emb_map, nbid[r], mbar_a);
    }
    MBAR_WAIT(mbar_a, 0);

    const int r0 = wid * 16;
    const int R0 = r0 + g, R1 = R0 + 8;

    // ---- pack A fragments once, 3 n-groups ----
    {
        const float* srow = &ssx[(wid >> 1) * SSW];
        uint32_t af[KTB][4];
        #pragma unroll
        for (int kk = 0; kk < KTB; ++kk) {
            const int c0 = kk * 16 + 2 * t;
            float2 h0 = *(const float2*)&A[R0 * AW + c0];
            float2 h1 = *(const float2*)&A[R1 * AW + c0];
            float2 h2 = *(const float2*)&A[R0 * AW + c0 + 8];
            float2 h3 = *(const float2*)&A[R1 * AW + c0 + 8];
            float2 s0 = *(const float2*)&srow[c0];
            float2 s1 = *(const float2*)&srow[c0 + 8];
            af[kk][0] = pack_bf16(h0.x * s0.x, h0.y * s0.y);
            af[kk][1] = pack_bf16(h1.x * s0.x, h1.y * s0.y);
            af[kk][2] = pack_bf16(h2.x * s1.x, h2.y * s1.y);
            af[kk][3] = pack_bf16(h3.x * s1.x, h3.y * s1.y);
        }
        const int ja = 2 * t, jb = ja + 1;
        float p0 = 0.f, p1 = 0.f;
        gemm_group<0, 5>(af, bsh, q1s, lane, ja, jb, p0, p1);
        gemm_group<5, 4>(af, bsh, q1s, lane, ja, jb, p0, p1);
        gemm_group<9, 4>(af, bsh, q1s, lane, ja, jb, p0, p1);
        p0 += __shfl_xor_sync(~0u, p0, 1); p0 += __shfl_xor_sync(~0u, p0, 2);
        p1 += __shfl_xor_sync(~0u, p1, 1); p1 += __shfl_xor_sync(~0u, p1, 2);
        if (t == 0) { score[R0] = p0; score[R1] = p1; }
    }
    __syncthreads();
    if (tid == 0) MBAR_INVAL(mbar_a);

    // ---- softmax (warps 0..1, warp = node) ----
    if (wid < NBA) {
        float sc = score[wid * 32 + lane];
        float mx = sc;
        #pragma unroll
        for (int o = 16; o > 0; o >>= 1) mx = fmaxf(mx, __shfl_xor_sync(~0u, mx, o));
        float e = __expf(sc - mx);
        float sum = e;
        #pragma unroll
        for (int o = 16; o > 0; o >>= 1) sum += __shfl_xor_sync(~0u, sum, o);
        score[wid * 32 + lane] = e / sum;
    }
    __syncthreads();

    // ---- msg on all 4 warps: warp = (node = wid>>1, d-half = wid&1) ----
    {
        const int node = wid >> 1;
        if (node0 + node < Ntot) {
            const float* at = &score[node * 32];
            const int dbase = (wid & 1) * 64;
            #pragma unroll
            for (int c = 0; c < 2; ++c) {
                int d = dbase + c * 32 + lane;
                if (d < D) {
                    float acc = 0.f;
                    const float* ap = &A[(node * 32) * AW + d];
                    #pragma unroll
                    for (int k = 0; k < Kn; ++k) acc += at[k] * ap[k * AW];
                    g_msg[(size_t)(node0 + node) * D + d] = acc;
                }
            }
        }
    }
}

// ---------------------------------------------------------------------------
// Kernel B (tf32 MMA): unchanged (297us config).
// ---------------------------------------------------------------------------
__global__ void __launch_bounds__(256, 3)
mlp_kernel(const int* __restrict__ nodes, const float* __restrict__ emb,
           const float* __restrict__ W2b, float* __restrict__ out, int Ntot)
{
    extern __shared__ float smf[];
    float* A   = smf;
    float* b2s = A + MN * SA2;
    int*   nid = (int*)(b2s + 104);

    const int tid  = threadIdx.x;
    const int wid  = tid >> 5;
    const int lane = tid & 31;
    const int g    = lane >> 2;
    const int t    = lane & 3;
    const int node0 = blockIdx.x * MN;
    if (node0 >= Ntot) return;

    if (tid < 104) b2s[tid] = (tid < D) ? W2b[tid] : 0.f;
    if (tid < MN) {
        int nn = node0 + tid; if (nn >= Ntot) nn = Ntot - 1;
        nid[tid] = nodes[nn];
    }
    __syncthreads();

    for (int r = wid; r < MN; r += 8) {
        int mrow = node0 + r; if (mrow >= Ntot) mrow = Ntot - 1;
        float* ar = &A[r * SA2];
        if (lane < 25) {
            ((float4*)ar)[lane] = ((const float4*)&emb[(size_t)nid[r] * D])[lane];
            ((float4*)(ar + 100))[lane] = ((const float4*)&g_msg[(size_t)mrow * D])[lane];
        }
    }
    __syncthreads();

    const int wg  = wid >> 2;
    const int r0  = (wid & 3) * 16;
    const int R0  = r0 + g, R1 = R0 + 8;
    const int nt0 = wg ? 7 : 0;
    const int ntn = wg ? 6 : 7;
    const int ja  = 2 * t, jb = ja + 1;

    #pragma unroll
    for (int layer = 0; layer < 2; ++layer) {
        float acc[7][4];
        for (int n = 0; n < ntn; ++n) {
            float ba = b2s[(nt0 + n) * 8 + ja], bb = b2s[(nt0 + n) * 8 + jb];
            acc[n][0] = ba; acc[n][1] = bb; acc[n][2] = ba; acc[n][3] = bb;
        }
        #pragma unroll
        for (int kk = 0; kk < KT2; ++kk) {
            const int c0 = kk * 8 + t;
            uint32_t a0 = f2tf32(A[R0 * SA2 + c0]);
            uint32_t a1 = f2tf32(A[R1 * SA2 + c0]);
            uint32_t a2 = f2tf32(A[R0 * SA2 + c0 + 4]);
            uint32_t a3 = f2tf32(A[R1 * SA2 + c0 + 4]);
            for (int n = 0; n < ntn; ++n) {
                float2 b = __ldg(&g_W2f[((nt0 + n) * KT2 + kk) * 32 + lane]);
                mma_tf32(acc[n][0], acc[n][1], acc[n][2], acc[n][3],
                         a0, a1, a2, a3,
                         __float_as_uint(b.x), __float_as_uint(b.y));
            }
        }
        __syncthreads();
        if (layer == 0) {
            for (int n = 0; n < ntn; ++n) {
                int j0 = (nt0 + n) * 8 + ja, j1 = j0 + 1;
                if (j0 < D) { A[R0 * SA2 + j0] = fmaxf(acc[n][0], 0.f);
                              A[R1 * SA2 + j0] = fmaxf(acc[n][2], 0.f); }
                if (j1 < D) { A[R0 * SA2 + j1] = fmaxf(acc[n][1], 0.f);
                              A[R1 * SA2 + j1] = fmaxf(acc[n][3], 0.f); }
            }
            __syncthreads();
        } else {
            int n0 = node0 + R0, n1 = node0 + R1;
            for (int n = 0; n < ntn; ++n) {
                int j0 = (nt0 + n) * 8 + ja, j1 = j0 + 1;
                if (n0 < Ntot) {
                    if (j0 < D) out[(size_t)n0 * D + j0] = fmaxf(acc[n][0], 0.f);
                    if (j1 < D) out[(size_t)n0 * D + j1] = fmaxf(acc[n][1], 0.f);
                }
                if (n1 < Ntot) {
                    if (j0 < D) out[(size_t)n1 * D + j0] = fmaxf(acc[n][2], 0.f);
                    if (j1 < D) out[(size_t)n1 * D + j1] = fmaxf(acc[n][3], 0.f);
                }
            }
        }
    }
}

// ---------------------------------------------------------------------------
typedef CUresult (*EncodeFn)(CUtensorMap*, CUtensorMapDataType, cuuint32_t, void*,
                             const cuuint64_t*, const cuuint64_t*, const cuuint32_t*,
                             const cuuint32_t*, CUtensorMapInterleave, CUtensorMapSwizzle,
                             CUtensorMapL2promotion, CUtensorMapFloatOOBfill);

extern "C" void kernel_launch(void* const* d_in, const int* in_sizes, int n_in,
                              void* d_out, int out_size)
{
    const int*   nodes = (const int*)  d_in[0];
    const int*   nei   = (const int*)  d_in[1];
    const float* wei   = (const float*)d_in[2];
    const float* s_vec = (const float*)d_in[3];
    const float* emb   = (const float*)d_in[4];
    const float* W1w   = (const float*)d_in[5];
    const float* W1b   = (const float*)d_in[6];
    const float* q1w   = (const float*)d_in[7];
    const float* W2w   = (const float*)d_in[8];
    const float* W2b   = (const float*)d_in[9];
    float* out = (float*)d_out;

    const int N = in_sizes[0];
    const unsigned long long V = (unsigned long long)(in_sizes[4] / D);

    // TMA descriptor for emb [V rows x 100 floats]; rows gathered one at a time.
    CUtensorMap emb_map;
    {
        void* fp = nullptr;
        cudaDriverEntryPointQueryResult st;
        cudaGetDriverEntryPoint("cuTensorMapEncodeTiled", &fp, cudaEnableDefault, &st);
        EncodeFn enc = (EncodeFn)fp;
        cuuint64_t dims[2]    = {(cuuint64_t)D, (cuuint64_t)V};
        cuuint64_t strides[1] = {(cuuint64_t)(D * 4)};
        cuuint32_t box[2]     = {(cuuint32_t)D, 1};
        cuuint32_t estr[2]    = {1, 1};
        enc(&emb_map, CU_TENSOR_MAP_DATA_TYPE_FLOAT32, 2, (void*)emb,
            dims, strides, box, estr,
            CU_TENSOR_MAP_INTERLEAVE_NONE, CU_TENSOR_MAP_SWIZZLE_NONE,
            CU_TENSOR_MAP_L2_PROMOTION_L2_128B, CU_TENSOR_MAP_FLOAT_OOB_FILL_NONE);
    }

    const int smemA = (M * AW + 104 + 104 + NBA * SSW + M + M) * 4 + 16;
    const int smemB = (MN * SA2 + 104) * 4 + MN * 4;

    cudaFuncSetAttribute(attn_kernel, cudaFuncAttributeMaxDynamicSharedMemorySize, smemA);
    cudaFuncSetAttribute(mlp_kernel,  cudaFuncAttributeMaxDynamicSharedMemorySize, smemB);

    const int prepN = NT * KTB * 32 + NT * KT2 * 32;
    prep_kernel<<<(prepN + 255) / 256, 256>>>(W1w, W2w);
    dummy_kernel<<<1, 32>>>();   // pad so ncu's profiled launch (#4) = full attn
    dummy_kernel<<<1, 32>>>();
    attn_kernel<<<(N + NBA - 1) / NBA, TA, smemA>>>(emb_map, nei, wei, s_vec, W1b, q1w, N);
    mlp_kernel<<<(N + MN - 1) / MN, 256, smemB>>>(nodes, emb, W2b, out, N);
}

// round 15
// speedup vs baseline: 1.3334x; 1.3334x over previous
#include <cuda_runtime.h>
#include <cstdint>

#define D    100
#define Kn   32
#define NBA  2            // attn nodes per block -> M = 64
#define M    64
#define AW   104          // A row stride (416B, 16B-aligned rows for bulk copy)
#define TA   128
#define NMAX 50000
#define NT   13
#define KTB  7            // attn k tiles of 16 (112, zero-padded from 101)
#define SSW  112
// mlp
#define MN   64
#define SA2  212
#define KT2  25

__device__ float g_msg[NMAX * D];
__device__ uint2  g_W1f[NT * KTB * 32];
__device__ float2 g_W2f[NT * KT2 * 32];

__device__ __forceinline__ float tanh_fast(float x) {
    float r; asm("tanh.approx.f32 %0, %1;" : "=f"(r) : "f"(x)); return r;
}
__device__ __forceinline__ uint32_t f2tf32(float x) {
    uint32_t r; asm("cvt.rna.tf32.f32 %0, %1;" : "=r"(r) : "f"(x)); return r;
}
__device__ __forceinline__ uint32_t pack_bf16(float lo, float hi) {
    uint32_t r; asm("cvt.rn.bf16x2.f32 %0, %1, %2;" : "=r"(r) : "f"(hi), "f"(lo)); return r;
}
__device__ __forceinline__ uint32_t smem_u32(const void* p) {
    uint32_t a;
    asm("{ .reg .u64 t; cvta.to.shared.u64 t, %1; cvt.u32.u64 %0, t; }" : "=r"(a) : "l"(p));
    return a;
}
__device__ __forceinline__ void mma_bf16(float& c0, float& c1, float& c2, float& c3,
                                         uint32_t a0, uint32_t a1, uint32_t a2, uint32_t a3,
                                         uint32_t b0, uint32_t b1) {
    asm volatile(
        "mma.sync.aligned.m16n8k16.row.col.f32.bf16.bf16.f32 "
        "{%0,%1,%2,%3}, {%4,%5,%6,%7}, {%8,%9}, {%0,%1,%2,%3};"
        : "+f"(c0), "+f"(c1), "+f"(c2), "+f"(c3)
        : "r"(a0), "r"(a1), "r"(a2), "r"(a3), "r"(b0), "r"(b1));
}
__device__ __forceinline__ void mma_tf32(float& c0, float& c1, float& c2, float& c3,
                                         uint32_t a0, uint32_t a1, uint32_t a2, uint32_t a3,
                                         uint32_t b0, uint32_t b1) {
    asm volatile(
        "mma.sync.aligned.m16n8k8.row.col.f32.tf32.tf32.f32 "
        "{%0,%1,%2,%3}, {%4,%5,%6,%7}, {%8,%9}, {%0,%1,%2,%3};"
        : "+f"(c0), "+f"(c1), "+f"(c2), "+f"(c3)
        : "r"(a0), "r"(a1), "r"(a2), "r"(a3), "r"(b0), "r"(b1));
}
#define MBAR_INIT(a, c) asm volatile("mbarrier.init.shared.b64 [%0], %1;" :: "r"(a), "r"(c) : "memory")
#define MBAR_EXPECT_TX(a, b) asm volatile("mbarrier.arrive.expect_tx.shared.b64 _, [%0], %1;" :: "r"(a), "r"(b) : "memory")
#define MBAR_INVAL(a) asm volatile("mbarrier.inval.shared.b64 [%0];" :: "r"(a) : "memory")
#define MBAR_WAIT(a, ph) do {                                                              \
    asm volatile("{\n\t.reg .pred P1;\n\tWL_%=:\n\t"                                       \
        "mbarrier.try_wait.parity.shared.b64 P1, [%0], %1, 0x989680;\n\t"                  \
        "@P1 bra.uni WD_%=;\n\tbra.uni WL_%=;\n\tWD_%=:\n\t}"                              \
        :: "r"(a), "r"(ph) : "memory"); } while (0)
// Non-tensor bulk copy: 400B emb row -> smem, completion via mbarrier tx bytes.
#define BULK_ROW(dst, src, bytes, mbar)                                                    \
    asm volatile("cp.async.bulk.shared::cluster.global.mbarrier::complete_tx::bytes "      \
        "[%0], [%1], %2, [%3];"                                                            \
        :: "r"(dst), "l"(src), "r"(bytes), "r"(mbar) : "memory")

// ---------------------------------------------------------------------------
__global__ void prep_kernel(const float* __restrict__ W1w, const float* __restrict__ W2w)
{
    int idx = blockIdx.x * blockDim.x + threadIdx.x;
    if (idx < NT * KTB * 32) {
        int lane = idx & 31, kk = (idx >> 5) % KTB, n = idx / (32 * KTB);
        int g = lane >> 2, t = lane & 3;
        int j = n * 8 + g;
        auto w1 = [&](int k) -> float {
            return (j < D && k < D + 1) ? W1w[k * D + j] : 0.f;
        };
        int k0 = kk * 16 + 2 * t;
        uint2 o;
        o.x = pack_bf16(w1(k0),     w1(k0 + 1));
        o.y = pack_bf16(w1(k0 + 8), w1(k0 + 9));
        g_W1f[idx] = o;
    } else if (idx < NT * KTB * 32 + NT * KT2 * 32) {
        int i2 = idx - NT * KTB * 32;
        int lane = i2 & 31, kk = (i2 >> 5) % KT2, n = i2 / (32 * KT2);
        int g = lane >> 2, t = lane & 3;
        int j = n * 8 + g;
        int k0 = kk * 8 + t, k1 = k0 + 4;
        float v0 = (j < D) ? W2w[k0 * D + j] : 0.f;
        float v1 = (j < D) ? W2w[k1 * D + j] : 0.f;
        float2 o;
        o.x = __uint_as_float(f2tf32(v0));
        o.y = __uint_as_float(f2tf32(v1));
        g_W2f[i2] = o;
    }
}

__global__ void dummy_kernel() {}

template<int N0, int NB>
__device__ __forceinline__ void gemm_group(const uint32_t af[KTB][4],
                                           const float* bsh, const float* q1s,
                                           int lane, int ja, int jb,
                                           float& p0, float& p1)
{
    float acc[NB][4];
    #pragma unroll
    for (int n = 0; n < NB; ++n) {
        float ba = bsh[(N0 + n) * 8 + ja], bb = bsh[(N0 + n) * 8 + jb];
        acc[n][0] = ba; acc[n][1] = bb; acc[n][2] = ba; acc[n][3] = bb;
    }
    #pragma unroll
    for (int kk = 0; kk < KTB; ++kk) {
        #pragma unroll
        for (int n = 0; n < NB; ++n) {
            uint2 b = __ldg(&g_W1f[((N0 + n) * KTB + kk) * 32 + lane]);
            mma_bf16(acc[n][0], acc[n][1], acc[n][2], acc[n][3],
                     af[kk][0], af[kk][1], af[kk][2], af[kk][3], b.x, b.y);
        }
    }
    #pragma unroll
    for (int n = 0; n < NB; ++n) {
        float qa = q1s[(N0 + n) * 8 + ja], qb = q1s[(N0 + n) * 8 + jb];
        p0 += qa * tanh_fast(acc[n][0]) + qb * tanh_fast(acc[n][1]);
        p1 += qa * tanh_fast(acc[n][2]) + qb * tanh_fast(acc[n][3]);
    }
}

// ---------------------------------------------------------------------------
// Kernel A: 2 nodes/block (M=64), 128 threads; gather via cp.async.bulk
// (one 400B row per thread, 64 parallel issues, mbarrier completion).
// ---------------------------------------------------------------------------
__global__ void __launch_bounds__(TA, 7)
attn_kernel(const int* __restrict__ nei, const float* __restrict__ wei,
            const float* __restrict__ s_vec, const float* __restrict__ emb,
            const float* __restrict__ W1b, const float* __restrict__ q1w, int Ntot)
{
    extern __shared__ __align__(16) float sm[];
    float* A    = sm;                    // [M][AW] + 8 pad (bulk fills cols 0..99)
    float* q1s  = A + M * AW + 8;        // [104]
    float* bsh  = q1s + 104;             // [104]
    float* ssx  = bsh + 104;             // [NBA][SSW]
    float* score= ssx + NBA * SSW;       // [M]
    int*   nbid = (int*)(score + M);     // [M]
    unsigned long long* mbar = (unsigned long long*)(nbid + M);

    const int tid  = threadIdx.x;
    const int wid  = tid >> 5;
    const int lane = tid & 31;
    const int g    = lane >> 2;
    const int t    = lane & 3;
    const int node0 = blockIdx.x * NBA;
    if (node0 >= Ntot) return;

    const uint32_t mbar_a = smem_u32(mbar);

    if (tid == 0) MBAR_INIT(mbar_a, 1);
    if (tid < M) {
        int r = tid, node = r >> 5, k = r & 31;
        int nn = node0 + node; if (nn >= Ntot) nn = Ntot - 1;
        nbid[r] = nei[nn * Kn + k];
        float* ar = &A[r * AW];
        ar[100] = wei[nn * Kn + k];
        ar[101] = 0.f; ar[102] = 0.f; ar[103] = 0.f;
    }
    if (tid < 8) A[M * AW + tid] = 0.f;          // overread pad past last row
    if (tid < 104) {
        q1s[tid] = (tid < D) ? q1w[tid] : 0.f;
        bsh[tid] = (tid < D) ? W1b[tid] : 0.f;
    }
    for (int i = tid; i < NBA * SSW; i += TA) {
        int node = i / SSW, d = i - node * SSW;
        int nn = node0 + node; if (nn >= Ntot) nn = Ntot - 1;
        ssx[i] = (d < D) ? s_vec[nn * D + d] : (d == D ? 1.f : 0.f);
    }
    __syncthreads();                              // mbar init + nbid visible

    // ---- bulk gather: 64 x 400B row copies, parallel issue ----
    if (tid == 0) MBAR_EXPECT_TX(mbar_a, M * D * 4);
    if (tid < M) {
        const uint32_t abase = smem_u32(A);
        BULK_ROW(abase + (uint32_t)tid * (AW * 4u),
                 emb + (size_t)nbid[tid] * D, D * 4, mbar_a);
    }
    MBAR_WAIT(mbar_a, 0);

    const int r0 = wid * 16;
    const int R0 = r0 + g, R1 = R0 + 8;

    // ---- pack A fragments once, 3 n-groups ----
    {
        const float* srow = &ssx[(wid >> 1) * SSW];
        uint32_t af[KTB][4];
        #pragma unroll
        for (int kk = 0; kk < KTB; ++kk) {
            const int c0 = kk * 16 + 2 * t;
            float2 h0 = *(const float2*)&A[R0 * AW + c0];
            float2 h1 = *(const float2*)&A[R1 * AW + c0];
            float2 h2 = *(const float2*)&A[R0 * AW + c0 + 8];
            float2 h3 = *(const float2*)&A[R1 * AW + c0 + 8];
            float2 s0 = *(const float2*)&srow[c0];
            float2 s1 = *(const float2*)&srow[c0 + 8];
            af[kk][0] = pack_bf16(h0.x * s0.x, h0.y * s0.y);
            af[kk][1] = pack_bf16(h1.x * s0.x, h1.y * s0.y);
            af[kk][2] = pack_bf16(h2.x * s1.x, h2.y * s1.y);
            af[kk][3] = pack_bf16(h3.x * s1.x, h3.y * s1.y);
        }
        const int ja = 2 * t, jb = ja + 1;
        float p0 = 0.f, p1 = 0.f;
        gemm_group<0, 5>(af, bsh, q1s, lane, ja, jb, p0, p1);
        gemm_group<5, 4>(af, bsh, q1s, lane, ja, jb, p0, p1);
        gemm_group<9, 4>(af, bsh, q1s, lane, ja, jb, p0, p1);
        p0 += __shfl_xor_sync(~0u, p0, 1); p0 += __shfl_xor_sync(~0u, p0, 2);
        p1 += __shfl_xor_sync(~0u, p1, 1); p1 += __shfl_xor_sync(~0u, p1, 2);
        if (t == 0) { score[R0] = p0; score[R1] = p1; }
    }
    __syncthreads();                              // all MBAR_WAITs done
    if (tid == 0) MBAR_INVAL(mbar_a);

    // ---- softmax (warps 0..1, warp = node) ----
    if (wid < NBA) {
        float sc = score[wid * 32 + lane];
        float mx = sc;
        #pragma unroll
        for (int o = 16; o > 0; o >>= 1) mx = fmaxf(mx, __shfl_xor_sync(~0u, mx, o));
        float e = __expf(sc - mx);
        float sum = e;
        #pragma unroll
        for (int o = 16; o > 0; o >>= 1) sum += __shfl_xor_sync(~0u, sum, o);
        score[wid * 32 + lane] = e / sum;
    }
    __syncthreads();

    // ---- msg on all 4 warps: warp = (node = wid>>1, d-half = wid&1) ----
    {
        const int node = wid >> 1;
        if (node0 + node < Ntot) {
            const float* at = &score[node * 32];
            const int dbase = (wid & 1) * 64;
            #pragma unroll
            for (int c = 0; c < 2; ++c) {
                int d = dbase + c * 32 + lane;
                if (d < D) {
                    float acc = 0.f;
                    const float* ap = &A[(node * 32) * AW + d];
                    #pragma unroll
                    for (int k = 0; k < Kn; ++k) acc += at[k] * ap[k * AW];
                    g_msg[(size_t)(node0 + node) * D + d] = acc;
                }
            }
        }
    }
}

// ---------------------------------------------------------------------------
// Kernel B (tf32 MMA): unchanged from R12 (297us config).
// ---------------------------------------------------------------------------
__global__ void __launch_bounds__(256, 3)
mlp_kernel(const int* __restrict__ nodes, const float* __restrict__ emb,
           const float* __restrict__ W2b, float* __restrict__ out, int Ntot)
{
    extern __shared__ float smf[];
    float* A   = smf;
    float* b2s = A + MN * SA2;
    int*   nid = (int*)(b2s + 104);

    const int tid  = threadIdx.x;
    const int wid  = tid >> 5;
    const int lane = tid & 31;
    const int g    = lane >> 2;
    const int t    = lane & 3;
    const int node0 = blockIdx.x * MN;
    if (node0 >= Ntot) return;

    if (tid < 104) b2s[tid] = (tid < D) ? W2b[tid] : 0.f;
    if (tid < MN) {
        int nn = node0 + tid; if (nn >= Ntot) nn = Ntot - 1;
        nid[tid] = nodes[nn];
    }
    __syncthreads();

    for (int r = wid; r < MN; r += 8) {
        int mrow = node0 + r; if (mrow >= Ntot) mrow = Ntot - 1;
        float* ar = &A[r * SA2];
        if (lane < 25) {
            ((float4*)ar)[lane] = ((const float4*)&emb[(size_t)nid[r] * D])[lane];
            ((float4*)(ar + 100))[lane] = ((const float4*)&g_msg[(size_t)mrow * D])[lane];
        }
    }
    __syncthreads();

    const int wg  = wid >> 2;
    const int r0  = (wid & 3) * 16;
    const int R0  = r0 + g, R1 = R0 + 8;
    const int nt0 = wg ? 7 : 0;
    const int ntn = wg ? 6 : 7;
    const int ja  = 2 * t, jb = ja + 1;

    #pragma unroll
    for (int layer = 0; layer < 2; ++layer) {
        float acc[7][4];
        for (int n = 0; n < ntn; ++n) {
            float ba = b2s[(nt0 + n) * 8 + ja], bb = b2s[(nt0 + n) * 8 + jb];
            acc[n][0] = ba; acc[n][1] = bb; acc[n][2] = ba; acc[n][3] = bb;
        }
        #pragma unroll
        for (int kk = 0; kk < KT2; ++kk) {
            const int c0 = kk * 8 + t;
            uint32_t a0 = f2tf32(A[R0 * SA2 + c0]);
            uint32_t a1 = f2tf32(A[R1 * SA2 + c0]);
            uint32_t a2 = f2tf32(A[R0 * SA2 + c0 + 4]);
            uint32_t a3 = f2tf32(A[R1 * SA2 + c0 + 4]);
            for (int n = 0; n < ntn; ++n) {
                float2 b = __ldg(&g_W2f[((nt0 + n) * KT2 + kk) * 32 + lane]);
                mma_tf32(acc[n][0], acc[n][1], acc[n][2], acc[n][3],
                         a0, a1, a2, a3,
                         __float_as_uint(b.x), __float_as_uint(b.y));
            }
        }
        __syncthreads();
        if (layer == 0) {
            for (int n = 0; n < ntn; ++n) {
                int j0 = (nt0 + n) * 8 + ja, j1 = j0 + 1;
                if (j0 < D) { A[R0 * SA2 + j0] = fmaxf(acc[n][0], 0.f);
                              A[R1 * SA2 + j0] = fmaxf(acc[n][2], 0.f); }
                if (j1 < D) { A[R0 * SA2 + j1] = fmaxf(acc[n][1], 0.f);
                              A[R1 * SA2 + j1] = fmaxf(acc[n][3], 0.f); }
            }
            __syncthreads();
        } else {
            int n0 = node0 + R0, n1 = node0 + R1;
            for (int n = 0; n < ntn; ++n) {
                int j0 = (nt0 + n) * 8 + ja, j1 = j0 + 1;
                if (n0 < Ntot) {
                    if (j0 < D) out[(size_t)n0 * D + j0] = fmaxf(acc[n][0], 0.f);
                    if (j1 < D) out[(size_t)n0 * D + j1] = fmaxf(acc[n][1], 0.f);
                }
                if (n1 < Ntot) {
                    if (j0 < D) out[(size_t)n1 * D + j0] = fmaxf(acc[n][2], 0.f);
                    if (j1 < D) out[(size_t)n1 * D + j1] = fmaxf(acc[n][3], 0.f);
                }
            }
        }
    }
}

// ---------------------------------------------------------------------------
extern "C" void kernel_launch(void* const* d_in, const int* in_sizes, int n_in,
                              void* d_out, int out_size)
{
    const int*   nodes = (const int*)  d_in[0];
    const int*   nei   = (const int*)  d_in[1];
    const float* wei   = (const float*)d_in[2];
    const float* s_vec = (const float*)d_in[3];
    const float* emb   = (const float*)d_in[4];
    const float* W1w   = (const float*)d_in[5];
    const float* W1b   = (const float*)d_in[6];
    const float* q1w   = (const float*)d_in[7];
    const float* W2w   = (const float*)d_in[8];
    const float* W2b   = (const float*)d_in[9];
    float* out = (float*)d_out;

    const int N = in_sizes[0];

    const int smemA = (M * AW + 8 + 104 + 104 + NBA * SSW + M + M) * 4 + 16;
    const int smemB = (MN * SA2 + 104) * 4 + MN * 4;

    cudaFuncSetAttribute(attn_kernel, cudaFuncAttributeMaxDynamicSharedMemorySize, smemA);
    cudaFuncSetAttribute(mlp_kernel,  cudaFuncAttributeMaxDynamicSharedMemorySize, smemB);

    const int prepN = NT * KTB * 32 + NT * KT2 * 32;
    prep_kernel<<<(prepN + 255) / 256, 256>>>(W1w, W2w);
    dummy_kernel<<<1, 32>>>();   // pad so ncu's profiled launch (#4) = full attn
    dummy_kernel<<<1, 32>>>();
    attn_kernel<<<(N + NBA - 1) / NBA, TA, smemA>>>(nei, wei, s_vec, emb, W1b, q1w, N);
    mlp_kernel<<<(N + MN - 1) / MN, 256, smemB>>>(nodes, emb, W2b, out, N);
}

// round 16
// speedup vs baseline: 1.3877x; 1.0408x over previous
#include <cuda_runtime.h>
#include <cstdint>

#define D    100
#define Kn   32
#define NBA  2            // attn nodes per block -> M = 64
#define M    64
#define AW   104          // A row stride (416B, 16B-aligned rows for bulk copy)
#define TA   128
#define NMAX 50000
#define NT   13
#define KTB  7            // attn k tiles of 16 (112, zero-padded from 101)
#define SSW  112
// mlp
#define MN   64
#define SA2  212
#define KT2  25

__device__ float g_msg[NMAX * D];
__device__ uint2  g_W1f[NT * KTB * 32];
__device__ float2 g_W2f[NT * KT2 * 32];

__device__ __forceinline__ float tanh_fast(float x) {
    float r; asm("tanh.approx.f32 %0, %1;" : "=f"(r) : "f"(x)); return r;
}
__device__ __forceinline__ uint32_t f2tf32(float x) {
    uint32_t r; asm("cvt.rna.tf32.f32 %0, %1;" : "=r"(r) : "f"(x)); return r;
}
__device__ __forceinline__ uint32_t pack_bf16(float lo, float hi) {
    uint32_t r; asm("cvt.rn.bf16x2.f32 %0, %1, %2;" : "=r"(r) : "f"(hi), "f"(lo)); return r;
}
__device__ __forceinline__ uint32_t smem_u32(const void* p) {
    uint32_t a;
    asm("{ .reg .u64 t; cvta.to.shared.u64 t, %1; cvt.u32.u64 %0, t; }" : "=r"(a) : "l"(p));
    return a;
}
__device__ __forceinline__ void mma_bf16(float& c0, float& c1, float& c2, float& c3,
                                         uint32_t a0, uint32_t a1, uint32_t a2, uint32_t a3,
                                         uint32_t b0, uint32_t b1) {
    asm volatile(
        "mma.sync.aligned.m16n8k16.row.col.f32.bf16.bf16.f32 "
        "{%0,%1,%2,%3}, {%4,%5,%6,%7}, {%8,%9}, {%0,%1,%2,%3};"
        : "+f"(c0), "+f"(c1), "+f"(c2), "+f"(c3)
        : "r"(a0), "r"(a1), "r"(a2), "r"(a3), "r"(b0), "r"(b1));
}
__device__ __forceinline__ void mma_tf32(float& c0, float& c1, float& c2, float& c3,
                                         uint32_t a0, uint32_t a1, uint32_t a2, uint32_t a3,
                                         uint32_t b0, uint32_t b1) {
    asm volatile(
        "mma.sync.aligned.m16n8k8.row.col.f32.tf32.tf32.f32 "
        "{%0,%1,%2,%3}, {%4,%5,%6,%7}, {%8,%9}, {%0,%1,%2,%3};"
        : "+f"(c0), "+f"(c1), "+f"(c2), "+f"(c3)
        : "r"(a0), "r"(a1), "r"(a2), "r"(a3), "r"(b0), "r"(b1));
}
#define MBAR_INIT(a, c) asm volatile("mbarrier.init.shared.b64 [%0], %1;" :: "r"(a), "r"(c) : "memory")
#define MBAR_EXPECT_TX(a, b) asm volatile("mbarrier.arrive.expect_tx.shared.b64 _, [%0], %1;" :: "r"(a), "r"(b) : "memory")
#define MBAR_WAIT(a, ph) do {                                                              \
    asm volatile("{\n\t.reg .pred P1;\n\tWL_%=:\n\t"                                       \
        "mbarrier.try_wait.parity.shared.b64 P1, [%0], %1, 0x989680;\n\t"                  \
        "@P1 bra.uni WD_%=;\n\tbra.uni WL_%=;\n\tWD_%=:\n\t}"                              \
        :: "r"(a), "r"(ph) : "memory"); } while (0)
#define BULK_ROW(dst, src, bytes, mbar)                                                    \
    asm volatile("cp.async.bulk.shared::cluster.global.mbarrier::complete_tx::bytes "      \
        "[%0], [%1], %2, [%3];"                                                            \
        :: "r"(dst), "l"(src), "r"(bytes), "r"(mbar) : "memory")

// ---------------------------------------------------------------------------
__global__ void prep_kernel(const float* __restrict__ W1w, const float* __restrict__ W2w)
{
    int idx = blockIdx.x * blockDim.x + threadIdx.x;
    if (idx < NT * KTB * 32) {
        int lane = idx & 31, kk = (idx >> 5) % KTB, n = idx / (32 * KTB);
        int g = lane >> 2, t = lane & 3;
        int j = n * 8 + g;
        auto w1 = [&](int k) -> float {
            return (j < D && k < D + 1) ? W1w[k * D + j] : 0.f;
        };
        int k0 = kk * 16 + 2 * t;
        uint2 o;
        o.x = pack_bf16(w1(k0),     w1(k0 + 1));
        o.y = pack_bf16(w1(k0 + 8), w1(k0 + 9));
        g_W1f[idx] = o;
    } else if (idx < NT * KTB * 32 + NT * KT2 * 32) {
        int i2 = idx - NT * KTB * 32;
        int lane = i2 & 31, kk = (i2 >> 5) % KT2, n = i2 / (32 * KT2);
        int g = lane >> 2, t = lane & 3;
        int j = n * 8 + g;
        int k0 = kk * 8 + t, k1 = k0 + 4;
        float v0 = (j < D) ? W2w[k0 * D + j] : 0.f;
        float v1 = (j < D) ? W2w[k1 * D + j] : 0.f;
        float2 o;
        o.x = __uint_as_float(f2tf32(v0));
        o.y = __uint_as_float(f2tf32(v1));
        g_W2f[i2] = o;
    }
}

__global__ void dummy_kernel() {}

template<int N0, int NB>
__device__ __forceinline__ void gemm_group(const uint32_t af[KTB][4],
                                           const float* bsh, const float* q1s,
                                           int lane, int ja, int jb,
                                           float& p0, float& p1)
{
    float acc[NB][4];
    #pragma unroll
    for (int n = 0; n < NB; ++n) {
        float ba = bsh[(N0 + n) * 8 + ja], bb = bsh[(N0 + n) * 8 + jb];
        acc[n][0] = ba; acc[n][1] = bb; acc[n][2] = ba; acc[n][3] = bb;
    }
    #pragma unroll
    for (int kk = 0; kk < KTB; ++kk) {
        #pragma unroll
        for (int n = 0; n < NB; ++n) {
            uint2 b = __ldg(&g_W1f[((N0 + n) * KTB + kk) * 32 + lane]);
            mma_bf16(acc[n][0], acc[n][1], acc[n][2], acc[n][3],
                     af[kk][0], af[kk][1], af[kk][2], af[kk][3], b.x, b.y);
        }
    }
    #pragma unroll
    for (int n = 0; n < NB; ++n) {
        float qa = q1s[(N0 + n) * 8 + ja], qb = q1s[(N0 + n) * 8 + jb];
        p0 += qa * tanh_fast(acc[n][0]) + qb * tanh_fast(acc[n][1]);
        p1 += qa * tanh_fast(acc[n][2]) + qb * tanh_fast(acc[n][3]);
    }
}

// ---------------------------------------------------------------------------
// Kernel A: 2 nodes/block (M=64), 128 threads. Fully per-warp front half:
// per-warp mbarrier + bulk gather of own 16 rows, per-warp q1/b/s copies,
// NO block sync until score exchange.
// ---------------------------------------------------------------------------
__global__ void __launch_bounds__(TA, 7)
attn_kernel(const int* __restrict__ nei, const float* __restrict__ wei,
            const float* __restrict__ s_vec, const float* __restrict__ emb,
            const float* __restrict__ W1b, const float* __restrict__ q1w, int Ntot)
{
    extern __shared__ __align__(16) float sm[];
    float* A    = sm;                    // [M][AW] + 8 pad
    float* wsm  = A + M * AW + 8;        // [4][208]  per-warp: q1 | bias
    float* ssw  = wsm + 4 * 208;         // [4][SSW]  per-warp s row (+1,+0 pad)
    float* score= ssw + 4 * SSW;         // [M]
    unsigned long long* mbar = (unsigned long long*)(score + M);  // [4]

    const int tid  = threadIdx.x;
    const int wid  = tid >> 5;
    const int lane = tid & 31;
    const int g    = lane >> 2;
    const int t    = lane & 3;
    const int node0 = blockIdx.x * NBA;
    if (node0 >= Ntot) return;

    const uint32_t mbar_w = smem_u32(mbar + wid);
    const int r0 = wid * 16;
    const int R0 = r0 + g, R1 = R0 + 8;

    // ---- per-warp: init mbar, gather own 16 rows (nbid in registers) ----
    if (lane == 0) MBAR_INIT(mbar_w, 1);
    __syncwarp();
    if (lane == 0) MBAR_EXPECT_TX(mbar_w, 16 * D * 4);
    float wv = 0.f;
    int r = r0 + (lane & 15);
    if (lane < 16) {
        int node = r >> 5, k = r & 31;
        int nn = node0 + node; if (nn >= Ntot) nn = Ntot - 1;
        int nb = nei[nn * Kn + k];
        wv = wei[nn * Kn + k];
        BULK_ROW(smem_u32(A) + (uint32_t)r * (AW * 4u),
                 emb + (size_t)nb * D, D * 4, mbar_w);
    }

    // ---- overlap bulk latency: per-warp q1/bias/s copies, wei/pad stores ----
    {
        float* wq = &wsm[wid * 208];
        for (int j = lane; j < 104; j += 32) {
            wq[j]       = (j < D) ? q1w[j] : 0.f;
            wq[104 + j] = (j < D) ? W1b[j] : 0.f;
        }
        const int node = wid >> 1;
        int nn = node0 + node; if (nn >= Ntot) nn = Ntot - 1;
        for (int j = lane; j < SSW; j += 32)
            ssw[wid * SSW + j] = (j < D) ? s_vec[nn * D + j] : (j == D ? 1.f : 0.f);
        if (lane < 16) {
            float* ar = &A[r * AW];
            ar[100] = wv; ar[101] = 0.f; ar[102] = 0.f; ar[103] = 0.f;
        }
        if (wid == 3 && lane >= 16 && lane < 24)   // pad past last row
            A[M * AW + lane - 16] = 0.f;
    }

    MBAR_WAIT(mbar_w, 0);    // only THIS warp's 16 rows
    __syncwarp();

    // ---- pack A fragments once, 3 n-groups (all per-warp state) ----
    {
        const float* srow = &ssw[wid * SSW];
        const float* q1s  = &wsm[wid * 208];
        const float* bsh  = q1s + 104;
        uint32_t af[KTB][4];
        #pragma unroll
        for (int kk = 0; kk < KTB; ++kk) {
            const int c0 = kk * 16 + 2 * t;
            float2 h0 = *(const float2*)&A[R0 * AW + c0];
            float2 h1 = *(const float2*)&A[R1 * AW + c0];
            float2 h2 = *(const float2*)&A[R0 * AW + c0 + 8];
            float2 h3 = *(const float2*)&A[R1 * AW + c0 + 8];
            float2 s0 = *(const float2*)&srow[c0];
            float2 s1 = *(const float2*)&srow[c0 + 8];
            af[kk][0] = pack_bf16(h0.x * s0.x, h0.y * s0.y);
            af[kk][1] = pack_bf16(h1.x * s0.x, h1.y * s0.y);
            af[kk][2] = pack_bf16(h2.x * s1.x, h2.y * s1.y);
            af[kk][3] = pack_bf16(h3.x * s1.x, h3.y * s1.y);
        }
        const int ja = 2 * t, jb = ja + 1;
        float p0 = 0.f, p1 = 0.f;
        gemm_group<0, 5>(af, bsh, q1s, lane, ja, jb, p0, p1);
        gemm_group<5, 4>(af, bsh, q1s, lane, ja, jb, p0, p1);
        gemm_group<9, 4>(af, bsh, q1s, lane, ja, jb, p0, p1);
        p0 += __shfl_xor_sync(~0u, p0, 1); p0 += __shfl_xor_sync(~0u, p0, 2);
        p1 += __shfl_xor_sync(~0u, p1, 1); p1 += __shfl_xor_sync(~0u, p1, 2);
        if (t == 0) { score[R0] = p0; score[R1] = p1; }
    }
    __syncthreads();          // first block-wide sync: scores + all A rows ready

    // ---- softmax (warps 0..1, warp = node) ----
    if (wid < NBA) {
        float sc = score[wid * 32 + lane];
        float mx = sc;
        #pragma unroll
        for (int o = 16; o > 0; o >>= 1) mx = fmaxf(mx, __shfl_xor_sync(~0u, mx, o));
        float e = __expf(sc - mx);
        float sum = e;
        #pragma unroll
        for (int o = 16; o > 0; o >>= 1) sum += __shfl_xor_sync(~0u, sum, o);
        score[wid * 32 + lane] = e / sum;
    }
    __syncthreads();

    // ---- msg on all 4 warps: warp = (node = wid>>1, d-half = wid&1) ----
    {
        const int node = wid >> 1;
        if (node0 + node < Ntot) {
            const float* at = &score[node * 32];
            const int dbase = (wid & 1) * 64;
            #pragma unroll
            for (int c = 0; c < 2; ++c) {
                int d = dbase + c * 32 + lane;
                if (d < D) {
                    float acc = 0.f;
                    const float* ap = &A[(node * 32) * AW + d];
                    #pragma unroll
                    for (int k = 0; k < Kn; ++k) acc += at[k] * ap[k * AW];
                    g_msg[(size_t)(node0 + node) * D + d] = acc;
                }
            }
        }
    }
}

// ---------------------------------------------------------------------------
// Kernel B (tf32 MMA): unchanged (295us config).
// ---------------------------------------------------------------------------
__global__ void __launch_bounds__(256, 3)
mlp_kernel(const int* __restrict__ nodes, const float* __restrict__ emb,
           const float* __restrict__ W2b, float* __restrict__ out, int Ntot)
{
    extern __shared__ float smf[];
    float* A   = smf;
    float* b2s = A + MN * SA2;
    int*   nid = (int*)(b2s + 104);

    const int tid  = threadIdx.x;
    const int wid  = tid >> 5;
    const int lane = tid & 31;
    const int g    = lane >> 2;
    const int t    = lane & 3;
    const int node0 = blockIdx.x * MN;
    if (node0 >= Ntot) return;

    if (tid < 104) b2s[tid] = (tid < D) ? W2b[tid] : 0.f;
    if (tid < MN) {
        int nn = node0 + tid; if (nn >= Ntot) nn = Ntot - 1;
        nid[tid] = nodes[nn];
    }
    __syncthreads();

    for (int r = wid; r < MN; r += 8) {
        int mrow = node0 + r; if (mrow >= Ntot) mrow = Ntot - 1;
        float* ar = &A[r * SA2];
        if (lane < 25) {
            ((float4*)ar)[lane] = ((const float4*)&emb[(size_t)nid[r] * D])[lane];
            ((float4*)(ar + 100))[lane] = ((const float4*)&g_msg[(size_t)mrow * D])[lane];
        }
    }
    __syncthreads();

    const int wg  = wid >> 2;
    const int r0  = (wid & 3) * 16;
    const int R0  = r0 + g, R1 = R0 + 8;
    const int nt0 = wg ? 7 : 0;
    const int ntn = wg ? 6 : 7;
    const int ja  = 2 * t, jb = ja + 1;

    #pragma unroll
    for (int layer = 0; layer < 2; ++layer) {
        float acc[7][4];
        for (int n = 0; n < ntn; ++n) {
            float ba = b2s[(nt0 + n) * 8 + ja], bb = b2s[(nt0 + n) * 8 + jb];
            acc[n][0] = ba; acc[n][1] = bb; acc[n][2] = ba; acc[n][3] = bb;
        }
        #pragma unroll
        for (int kk = 0; kk < KT2; ++kk) {
            const int c0 = kk * 8 + t;
            uint32_t a0 = f2tf32(A[R0 * SA2 + c0]);
            uint32_t a1 = f2tf32(A[R1 * SA2 + c0]);
            uint32_t a2 = f2tf32(A[R0 * SA2 + c0 + 4]);
            uint32_t a3 = f2tf32(A[R1 * SA2 + c0 + 4]);
            for (int n = 0; n < ntn; ++n) {
                float2 b = __ldg(&g_W2f[((nt0 + n) * KT2 + kk) * 32 + lane]);
                mma_tf32(acc[n][0], acc[n][1], acc[n][2], acc[n][3],
                         a0, a1, a2, a3,
                         __float_as_uint(b.x), __float_as_uint(b.y));
            }
        }
        __syncthreads();
        if (layer == 0) {
            for (int n = 0; n < ntn; ++n) {
                int j0 = (nt0 + n) * 8 + ja, j1 = j0 + 1;
                if (j0 < D) { A[R0 * SA2 + j0] = fmaxf(acc[n][0], 0.f);
                              A[R1 * SA2 + j0] = fmaxf(acc[n][2], 0.f); }
                if (j1 < D) { A[R0 * SA2 + j1] = fmaxf(acc[n][1], 0.f);
                              A[R1 * SA2 + j1] = fmaxf(acc[n][3], 0.f); }
            }
            __syncthreads();
        } else {
            int n0 = node0 + R0, n1 = node0 + R1;
            for (int n = 0; n < ntn; ++n) {
                int j0 = (nt0 + n) * 8 + ja, j1 = j0 + 1;
                if (n0 < Ntot) {
                    if (j0 < D) out[(size_t)n0 * D + j0] = fmaxf(acc[n][0], 0.f);
                    if (j1 < D) out[(size_t)n0 * D + j1] = fmaxf(acc[n][1], 0.f);
                }
                if (n1 < Ntot) {
                    if (j0 < D) out[(size_t)n1 * D + j0] = fmaxf(acc[n][2], 0.f);
                    if (j1 < D) out[(size_t)n1 * D + j1] = fmaxf(acc[n][3], 0.f);
                }
            }
        }
    }
}

// ---------------------------------------------------------------------------
extern "C" void kernel_launch(void* const* d_in, const int* in_sizes, int n_in,
                              void* d_out, int out_size)
{
    const int*   nodes = (const int*)  d_in[0];
    const int*   nei   = (const int*)  d_in[1];
    const float* wei   = (const float*)d_in[2];
    const float* s_vec = (const float*)d_in[3];
    const float* emb   = (const float*)d_in[4];
    const float* W1w   = (const float*)d_in[5];
    const float* W1b   = (const float*)d_in[6];
    const float* q1w   = (const float*)d_in[7];
    const float* W2w   = (const float*)d_in[8];
    const float* W2b   = (const float*)d_in[9];
    float* out = (float*)d_out;

    const int N = in_sizes[0];

    const int smemA = (M * AW + 8 + 4 * 208 + 4 * SSW + M) * 4 + 32;
    const int smemB = (MN * SA2 + 104) * 4 + MN * 4;

    cudaFuncSetAttribute(attn_kernel, cudaFuncAttributeMaxDynamicSharedMemorySize, smemA);
    cudaFuncSetAttribute(mlp_kernel,  cudaFuncAttributeMaxDynamicSharedMemorySize, smemB);

    const int prepN = NT * KTB * 32 + NT * KT2 * 32;
    prep_kernel<<<(prepN + 255) / 256, 256>>>(W1w, W2w);
    dummy_kernel<<<1, 32>>>();   // pad so ncu's profiled launch (#4) = full attn
    dummy_kernel<<<1, 32>>>();
    attn_kernel<<<(N + NBA - 1) / NBA, TA, smemA>>>(nei, wei, s_vec, emb, W1b, q1w, N);
    mlp_kernel<<<(N + MN - 1) / MN, 256, smemB>>>(nodes, emb, W2b, out, N);
}